// round 15
// baseline (speedup 1.0000x reference)
#include <cuda_runtime.h>
#include <cstdint>
#include <cstddef>

#define NJ 24
#define NGROUPS 6
#define UPG 64                          // units per group (2 warps)
#define THREADS (NGROUPS * UPG)         // 384
#define FPSLAB 32                       // frames per slab (UPG/2)
#define ROW_Q 37                        // padded pose row: 36 f4 data + 1 pad (odd -> conflict-free)
#define ROW_BYTES (ROW_Q * 16)          // 592
#define GROUP_SLAB_BYTES (UPG * ROW_BYTES)      // 37888
#define DYN_SMEM (NGROUPS * GROUP_SLAB_BYTES)   // 227328

__device__ float g_partials[16384];
__device__ unsigned int g_count = 0;

__device__ __forceinline__ float rsq(float x) {
    float y = __int_as_float(0x5f3759dfu - (__float_as_uint(x) >> 1));
    float hx = 0.5f * x;
    y = y * (1.5f - hx * y * y);
    y = y * (1.5f - hx * y * y);
    return y;
}

__device__ __forceinline__ void bulk_g2s(uint32_t dst, const void* src,
                                         uint32_t bytes, uint32_t mbar) {
    asm volatile(
        "cp.async.bulk.shared::cta.global.mbarrier::complete_tx::bytes [%0], [%1], %2, [%3];"
        :: "r"(dst), "l"(src), "r"(bytes), "r"(mbar) : "memory");
}
__device__ __forceinline__ void mbar_init(uint32_t mbar, uint32_t count) {
    asm volatile("mbarrier.init.shared.b64 [%0], %1;" :: "r"(mbar), "r"(count) : "memory");
}
__device__ __forceinline__ void mbar_arrive_expect_tx(uint32_t mbar, uint32_t tx) {
    asm volatile("mbarrier.arrive.expect_tx.shared.b64 _, [%0], %1;"
                 :: "r"(mbar), "r"(tx) : "memory");
}
__device__ __forceinline__ void mbar_wait(uint32_t mbar, uint32_t parity) {
    asm volatile(
        "{\n\t"
        ".reg .pred P;\n\t"
        "WL_%=:\n\t"
        "mbarrier.try_wait.parity.acquire.cta.shared::cta.b64 P, [%0], %1, 0x989680;\n\t"
        "@P bra.uni WD_%=;\n\t"
        "bra.uni WL_%=;\n\t"
        "WD_%=:\n\t"
        "}"
        :: "r"(mbar), "r"(parity) : "memory");
}

// Persistent hybrid kernel: grid = #SMs, 384 threads = 12 warps = 6 groups
// of 64 units. Unit u of a group: frame (u>>1) of its slab, pose (u&1).
// POSE rows (576B, the wavefront-dominant traffic) stream via cp.async.bulk
// into thread-private padded smem rows; OFFSET rows (288B) are read directly
// from gmem (cheap wavefronts, adds MLP). Mainloop is barrier-free: each
// thread refills its own row right after consuming it (group mbarrier,
// count=64, collects arrivals + tx bytes).
__global__ void __launch_bounds__(THREADS, 1)
ee_loss_kernel(const float* __restrict__ poseA, const float* __restrict__ poseB,
               const float* __restrict__ offA,  const float* __restrict__ offB,
               const float* __restrict__ tA,    const float* __restrict__ tB,
               float* __restrict__ out,
               int F, float inv_count)
{
    constexpr int PARENTS[NJ] = {-1,0,0,0,1,2,3,4,5,6,7,8,9,9,9,12,13,14,16,17,18,19,20,21};
    constexpr bool IS_EE[NJ] = {false,false,false,false,false,false,false,false,false,false,
                                true, true, false,false,false,true, false,false,false,false,
                                false,false,true, true};
    constexpr int EE_SLOT[NJ] = {-1,-1,-1,-1,-1,-1,-1,-1,-1,-1,
                                  0, 1,-1,-1,-1, 2,-1,-1,-1,-1,
                                 -1,-1, 3, 4};
    constexpr int END_SITES[5] = {10,11,15,22,23};

    extern __shared__ float4 dyn[];
    __shared__ uint64_t mbar_store[NGROUPS];
    __shared__ float  s_iS[2][3];
    __shared__ float  s_c[2][15];
    __shared__ float  s_wsum[12];
    __shared__ double s_ddbl[12];
    __shared__ bool   s_last;

    const int tid   = threadIdx.x;
    const int warp  = tid >> 5;
    const int lane  = tid & 31;
    const int group = tid / UPG;
    const int u     = tid % UPG;
    const int pb    = u & 1;
    const int grid  = gridDim.x;
    const int bid   = blockIdx.x;

    if (tid < NGROUPS)
        mbar_init((uint32_t)__cvta_generic_to_shared(&mbar_store[tid]), UPG);
    if (tid == 0) {
        float mnA[3], mxA[3], mnB[3], mxB[3];
#pragma unroll
        for (int a = 0; a < 3; ++a) { mnA[a] = mxA[a] = tA[a]; mnB[a] = mxB[a] = tB[a]; }
#pragma unroll
        for (int j = 1; j < NJ; ++j) {
#pragma unroll
            for (int a = 0; a < 3; ++a) {
                const float va = tA[j * 3 + a];
                const float vb = tB[j * 3 + a];
                mnA[a] = fminf(mnA[a], va); mxA[a] = fmaxf(mxA[a], va);
                mnB[a] = fminf(mnB[a], vb); mxB[a] = fmaxf(mxB[a], vb);
            }
        }
#pragma unroll
        for (int a = 0; a < 3; ++a) {
            s_iS[0][a] = 1.0f / (mxA[a] - mnA[a]);
            s_iS[1][a] = 1.0f / (mxB[a] - mnB[a]);
        }
#pragma unroll
        for (int e = 0; e < 5; ++e) {
#pragma unroll
            for (int a = 0; a < 3; ++a) {
                s_c[0][e * 3 + a] = tA[END_SITES[e] * 3 + a] * s_iS[0][a];
                s_c[1][e * 3 + a] = tB[END_SITES[e] * 3 + a] * s_iS[1][a];
            }
        }
    }
    __syncthreads();

    const int n_groups = grid * NGROUPS;
    const int gidx     = bid * NGROUPS + group;
    const int S        = (F + FPSLAB - 1) / FPSLAB;
    const int K        = (S > gidx) ? ((S - 1 - gidx) / n_groups + 1) : 0;

    const float4* __restrict__ prow = dyn + (size_t)(group * UPG + u) * ROW_Q;
    const uint32_t row_u = (uint32_t)__cvta_generic_to_shared(dyn)
                         + (uint32_t)((group * UPG + u) * ROW_BYTES);
    const uint32_t mb    = (uint32_t)__cvta_generic_to_shared(&mbar_store[group]);

    const float* __restrict__ poseSrc = pb ? poseB : poseA;
    const float4* __restrict__ offSrc = reinterpret_cast<const float4*>(pb ? offB : offA);

    // slab k -> clamped start frame
    auto slab_start = [&](int k) {
        int st = (gidx + k * n_groups) * FPSLAB;
        if (st + FPSLAB > F) st = F - FPSLAB;
        return st;
    };

    float acc = 0.0f;
    uint32_t ph = 0;

    if (K > 0) {
        mbar_arrive_expect_tx(mb, 576);
        bulk_g2s(row_u, poseSrc + (size_t)(slab_start(0) + (u >> 1)) * 144, 576, mb);
    }

    for (int i = 0; i < K; ++i) {
        mbar_wait(mb, ph);
        ph ^= 1u;

        const int raw_st = (gidx + i * n_groups) * FPSLAB;
        int st = raw_st, fresh = 0;
        if (st + FPSLAB > F) { st = F - FPSLAB; fresh = raw_st - st; }
        const int fl = u >> 1;                 // frame-local
        const bool contrib = (fl >= fresh);
        const int frame = st + fl;

        const float4* __restrict__ uv = offSrc + (size_t)frame * 18;

        // ---- single-pose FK from smem pose row + gmem offsets ----
        float O[NJ][9];
        float P[NJ][3];
        float4 q0, q1, q2, u0, u1, u2;
#pragma unroll
        for (int j = 0; j < NJ; ++j) {
            if ((j & 1) == 0) {
                const int bb = (3 * j) / 2;
                q0 = prow[bb]; q1 = prow[bb + 1]; q2 = prow[bb + 2];
            }
            float a0, a1, a2, a3, a4, a5;
            if ((j & 1) == 0) { a0 = q0.x; a1 = q0.y; a2 = q0.z; a3 = q0.w; a4 = q1.x; a5 = q1.y; }
            else              { a0 = q1.z; a1 = q1.w; a2 = q2.x; a3 = q2.y; a4 = q2.z; a5 = q2.w; }

            if ((j & 3) == 0) {
                const int bb = (3 * j) / 4;
                u0 = uv[bb]; u1 = uv[bb + 1]; u2 = uv[bb + 2];
            }
            float ox, oy, oz;
            switch (j & 3) {
                case 0:  ox = u0.x; oy = u0.y; oz = u0.z; break;
                case 1:  ox = u0.w; oy = u1.x; oz = u1.y; break;
                case 2:  ox = u1.z; oy = u1.w; oz = u2.x; break;
                default: ox = u2.y; oy = u2.z; oz = u2.w; break;
            }

            float r0 = 0.f, r1 = 0.f, r2 = 0.f, r3 = 0.f, r4 = 0.f,
                  r5 = 0.f, r6 = 0.f, r7 = 0.f, r8 = 0.f;
            if (!IS_EE[j]) {
                const float n1 = a0 * a0 + a1 * a1 + a2 * a2;
                const float i1 = rsq(n1);
                r0 = a0 * i1; r1 = a1 * i1; r2 = a2 * i1;
                const float d  = r0 * a3 + r1 * a4 + r2 * a5;
                const float c0 = a3 - d * r0;
                const float c1 = a4 - d * r1;
                const float c2 = a5 - d * r2;
                const float n2 = c0 * c0 + c1 * c1 + c2 * c2;
                const float i2 = rsq(n2);
                r3 = c0 * i2; r4 = c1 * i2; r5 = c2 * i2;
                r6 = r1 * r5 - r2 * r4;
                r7 = r2 * r3 - r0 * r5;
                r8 = r0 * r4 - r1 * r3;
            }

            if (j == 0) {
                P[0][0] = ox; P[0][1] = oy; P[0][2] = oz;
                O[0][0] = r0; O[0][1] = r1; O[0][2] = r2;
                O[0][3] = r3; O[0][4] = r4; O[0][5] = r5;
                O[0][6] = r6; O[0][7] = r7; O[0][8] = r8;
            } else {
                const int p = PARENTS[j];
                const float px = O[p][0] * ox + O[p][1] * oy + O[p][2] * oz + P[p][0];
                const float py = O[p][3] * ox + O[p][4] * oy + O[p][5] * oz + P[p][1];
                const float pz = O[p][6] * ox + O[p][7] * oy + O[p][8] * oz + P[p][2];
                if (IS_EE[j]) {
                    // immediate loss vs partner lane (A<->B of same frame)
                    const int sl = EE_SLOT[j];
                    const float v0 = px * s_iS[pb][0] - s_c[pb][sl * 3 + 0];
                    const float v1 = py * s_iS[pb][1] - s_c[pb][sl * 3 + 1];
                    const float v2 = pz * s_iS[pb][2] - s_c[pb][sl * 3 + 2];
                    const float w0 = __shfl_xor_sync(0xFFFFFFFFu, v0, 1);
                    const float w1 = __shfl_xor_sync(0xFFFFFFFFu, v1, 1);
                    const float w2 = __shfl_xor_sync(0xFFFFFFFFu, v2, 1);
                    if (contrib) {
                        const float d0 = v0 - w0, d1 = v1 - w1, d2 = v2 - w2;
                        acc = fmaf(d0, d0, acc);
                        acc = fmaf(d1, d1, acc);
                        acc = fmaf(d2, d2, acc);
                    }
                } else {
                    P[j][0] = px; P[j][1] = py; P[j][2] = pz;
                    O[j][0] = O[p][0] * r0 + O[p][1] * r3 + O[p][2] * r6;
                    O[j][1] = O[p][0] * r1 + O[p][1] * r4 + O[p][2] * r7;
                    O[j][2] = O[p][0] * r2 + O[p][1] * r5 + O[p][2] * r8;
                    O[j][3] = O[p][3] * r0 + O[p][4] * r3 + O[p][5] * r6;
                    O[j][4] = O[p][3] * r1 + O[p][4] * r4 + O[p][5] * r7;
                    O[j][5] = O[p][3] * r2 + O[p][4] * r5 + O[p][5] * r8;
                    O[j][6] = O[p][6] * r0 + O[p][7] * r3 + O[p][8] * r6;
                    O[j][7] = O[p][6] * r1 + O[p][7] * r4 + O[p][8] * r7;
                    O[j][8] = O[p][6] * r2 + O[p][7] * r5 + O[p][8] * r8;
                }
            }
        }

        // This thread's row is private and fully consumed -> refill now.
        if (i + 1 < K) {
            mbar_arrive_expect_tx(mb, 576);
            bulk_g2s(row_u, poseSrc + (size_t)(slab_start(i + 1) + (u >> 1)) * 144, 576, mb);
        }
    }

    // ---- deterministic in-block reduction (12 warps) ----
#pragma unroll
    for (int o = 16; o > 0; o >>= 1)
        acc += __shfl_xor_sync(0xFFFFFFFFu, acc, o);
    if (lane == 0) s_wsum[warp] = acc;
    __syncthreads();

    if (tid == 0) {
        float bs = 0.0f;
#pragma unroll
        for (int w = 0; w < 12; ++w) bs += s_wsum[w];
        g_partials[bid] = bs;
        __threadfence();
        const unsigned int done = atomicAdd(&g_count, 1u);
        s_last = (done == (unsigned int)(grid - 1));
    }
    __syncthreads();

    // Last block reduces all partials in a FIXED order -> deterministic.
    if (s_last) {
        double ds = 0.0;
        for (int i = tid; i < grid; i += THREADS)
            ds += (double)g_partials[i];
#pragma unroll
        for (int o = 16; o > 0; o >>= 1)
            ds += __shfl_xor_sync(0xFFFFFFFFu, ds, o);
        if (lane == 0) s_ddbl[warp] = ds;
        __syncthreads();
        if (tid == 0) {
            double t = 0.0;
#pragma unroll
            for (int w = 0; w < 12; ++w) t += s_ddbl[w];
            out[0] = (float)(t * (double)inv_count);
            g_count = 0;   // reset for next graph replay
        }
    }
}

extern "C" void kernel_launch(void* const* d_in, const int* in_sizes, int n_in,
                              void* d_out, int out_size)
{
    const float* poseA = (const float*)d_in[0];
    const float* poseB = (const float*)d_in[1];
    const float* offA  = (const float*)d_in[2];
    const float* offB  = (const float*)d_in[3];
    const float* tA    = (const float*)d_in[4];
    const float* tB    = (const float*)d_in[5];
    float* out = (float*)d_out;

    const int F = in_sizes[0] / (NJ * 6);
    int dev = 0, sms = 148;
    cudaGetDevice(&dev);
    cudaDeviceGetAttribute(&sms, cudaDevAttrMultiProcessorCount, dev);
    if (sms > 16384) sms = 16384;

    cudaFuncSetAttribute(ee_loss_kernel,
                         cudaFuncAttributeMaxDynamicSharedMemorySize, DYN_SMEM);

    // Each (frame,pose) pair's squared diff is accumulated twice -> extra /2.
    const float inv_count = 1.0f / ((float)F * 15.0f * 2.0f);
    ee_loss_kernel<<<sms, THREADS, DYN_SMEM>>>(poseA, poseB, offA, offB, tA, tB,
                                               out, F, inv_count);
}

// round 16
// speedup vs baseline: 1.8151x; 1.8151x over previous
#include <cuda_runtime.h>
#include <cstddef>

#define NJ 24

__device__ float g_partials[16384];
__device__ unsigned int g_count = 0;

// Fast inverse sqrt on the FMA pipe (avoids MUFU throughput bound).
__device__ __forceinline__ float rsq(float x) {
    float y = __int_as_float(0x5f3759dfu - (__float_as_uint(x) >> 1));
    float hx = 0.5f * x;
    y = y * (1.5f - hx * y * y);
    y = y * (1.5f - hx * y * y);
    return y;
}

// 256-bit global load (Blackwell LDG.E.256). p must be 32B-aligned.
__device__ __forceinline__ void ldg256(const float* __restrict__ p, float* w) {
    asm("ld.global.v8.f32 {%0,%1,%2,%3,%4,%5,%6,%7}, [%8];"
        : "=f"(w[0]), "=f"(w[1]), "=f"(w[2]), "=f"(w[3]),
          "=f"(w[4]), "=f"(w[5]), "=f"(w[6]), "=f"(w[7])
        : "l"(p));
}

// Forward kinematics for one frame of one pose; emits the 5 end-site positions.
// poseF: 144 floats (24 x 6) = 18 x 32B chunks; offF: 72 floats = 9 x 32B.
// All loads are LDG.256: halves the L1tex wavefront count vs LDG.128 at this
// 576B row stride (each wavefront delivers 32B instead of 16B per lane).
__device__ __forceinline__ void fk_ee(const float* __restrict__ poseF,
                                      const float* __restrict__ offF,
                                      float ee[5][3])
{
    constexpr int PARENTS[NJ] = {-1,0,0,0,1,2,3,4,5,6,7,8,9,9,9,12,13,14,16,17,18,19,20,21};
    constexpr bool IS_EE[NJ] = {false,false,false,false,false,false,false,false,false,false,
                                true, true, false,false,false,true, false,false,false,false,
                                false,false,true, true};
    constexpr int EE_SLOT[NJ] = {-1,-1,-1,-1,-1,-1,-1,-1,-1,-1,
                                  0, 1,-1,-1,-1, 2,-1,-1,-1,-1,
                                 -1,-1, 3, 4};

    float O[NJ][9];   // global orientations (row-major); scalarized by full unroll
    float P[NJ][3];   // global positions
    float pw[24];     // pose window: 4 joints (24 floats = 3 x v8)
    float ow[24];     // offset window: 8 joints (24 floats = 3 x v8)

#pragma unroll
    for (int i = 0; i < NJ; ++i) {
        if ((i & 3) == 0) {           // refill pose window: floats 6i..6i+23
            ldg256(poseF + 6 * i,      pw);
            ldg256(poseF + 6 * i + 8,  pw + 8);
            ldg256(poseF + 6 * i + 16, pw + 16);
        }
        const int m = 6 * (i & 3);
        const float a0 = pw[m],     a1 = pw[m + 1], a2 = pw[m + 2];
        const float a3 = pw[m + 3], a4 = pw[m + 4], a5 = pw[m + 5];

        if ((i & 7) == 0) {           // refill offset window: floats 3i..3i+23
            ldg256(offF + 3 * i,      ow);
            ldg256(offF + 3 * i + 8,  ow + 8);
            ldg256(offF + 3 * i + 16, ow + 16);
        }
        const int t = 3 * (i & 7);
        const float ox = ow[t], oy = ow[t + 1], oz = ow[t + 2];

        // 6D -> rotation matrix (rows b1,b2,b3). Skipped for leaf end-sites.
        float r0 = 0.f, r1 = 0.f, r2 = 0.f, r3 = 0.f, r4 = 0.f,
              r5 = 0.f, r6 = 0.f, r7 = 0.f, r8 = 0.f;
        if (!IS_EE[i]) {
            const float n1 = a0 * a0 + a1 * a1 + a2 * a2;
            const float i1 = rsq(n1);
            r0 = a0 * i1; r1 = a1 * i1; r2 = a2 * i1;
            const float d  = r0 * a3 + r1 * a4 + r2 * a5;
            const float c0 = a3 - d * r0;
            const float c1 = a4 - d * r1;
            const float c2 = a5 - d * r2;
            const float n2 = c0 * c0 + c1 * c1 + c2 * c2;
            const float i2 = rsq(n2);
            r3 = c0 * i2; r4 = c1 * i2; r5 = c2 * i2;
            r6 = r1 * r5 - r2 * r4;
            r7 = r2 * r3 - r0 * r5;
            r8 = r0 * r4 - r1 * r3;
        }

        if (i == 0) {
            P[0][0] = ox; P[0][1] = oy; P[0][2] = oz;
            O[0][0] = r0; O[0][1] = r1; O[0][2] = r2;
            O[0][3] = r3; O[0][4] = r4; O[0][5] = r5;
            O[0][6] = r6; O[0][7] = r7; O[0][8] = r8;
        } else {
            const int p = PARENTS[i];
            const float px = O[p][0] * ox + O[p][1] * oy + O[p][2] * oz + P[p][0];
            const float py = O[p][3] * ox + O[p][4] * oy + O[p][5] * oz + P[p][1];
            const float pz = O[p][6] * ox + O[p][7] * oy + O[p][8] * oz + P[p][2];
            if (IS_EE[i]) {
                const int s = EE_SLOT[i];
                ee[s][0] = px; ee[s][1] = py; ee[s][2] = pz;
            } else {
                P[i][0] = px; P[i][1] = py; P[i][2] = pz;
                // O[i] = O[p] @ R
                O[i][0] = O[p][0] * r0 + O[p][1] * r3 + O[p][2] * r6;
                O[i][1] = O[p][0] * r1 + O[p][1] * r4 + O[p][2] * r7;
                O[i][2] = O[p][0] * r2 + O[p][1] * r5 + O[p][2] * r8;
                O[i][3] = O[p][3] * r0 + O[p][4] * r3 + O[p][5] * r6;
                O[i][4] = O[p][3] * r1 + O[p][4] * r4 + O[p][5] * r7;
                O[i][5] = O[p][3] * r2 + O[p][4] * r5 + O[p][5] * r8;
                O[i][6] = O[p][6] * r0 + O[p][7] * r3 + O[p][8] * r6;
                O[i][7] = O[p][6] * r1 + O[p][7] * r4 + O[p][8] * r7;
                O[i][8] = O[p][6] * r2 + O[p][7] * r5 + O[p][8] * r8;
            }
        }
    }
}

__global__ void __launch_bounds__(128)
ee_loss_kernel(const float* __restrict__ poseA, const float* __restrict__ poseB,
               const float* __restrict__ offA,  const float* __restrict__ offB,
               const float* __restrict__ tA,    const float* __restrict__ tB,
               float* __restrict__ out,
               int F, int nb, float inv_count)
{
    constexpr int END_SITES[5] = {10,11,15,22,23};
    __shared__ float s_iSA[3], s_iSB[3], s_c[15];   // c = tEA*iSA - tEB*iSB
    __shared__ float s_wsum[4];
    __shared__ bool  s_last;
    __shared__ double s_dsum[128];

    if (threadIdx.x == 0) {
        float mnA[3], mxA[3], mnB[3], mxB[3];
#pragma unroll
        for (int a = 0; a < 3; ++a) {
            mnA[a] = mxA[a] = tA[a];
            mnB[a] = mxB[a] = tB[a];
        }
#pragma unroll
        for (int j = 1; j < NJ; ++j) {
#pragma unroll
            for (int a = 0; a < 3; ++a) {
                const float va = tA[j * 3 + a];
                const float vb = tB[j * 3 + a];
                mnA[a] = fminf(mnA[a], va); mxA[a] = fmaxf(mxA[a], va);
                mnB[a] = fminf(mnB[a], vb); mxB[a] = fmaxf(mxB[a], vb);
            }
        }
        float iSA[3], iSB[3];
#pragma unroll
        for (int a = 0; a < 3; ++a) {
            iSA[a] = 1.0f / (mxA[a] - mnA[a]);
            iSB[a] = 1.0f / (mxB[a] - mnB[a]);
            s_iSA[a] = iSA[a];
            s_iSB[a] = iSB[a];
        }
#pragma unroll
        for (int e = 0; e < 5; ++e) {
#pragma unroll
            for (int a = 0; a < 3; ++a) {
                s_c[e * 3 + a] = tA[END_SITES[e] * 3 + a] * iSA[a]
                               - tB[END_SITES[e] * 3 + a] * iSB[a];
            }
        }
    }
    __syncthreads();

    const int frame = blockIdx.x * blockDim.x + threadIdx.x;
    float s = 0.0f;
    if (frame < F) {
        float eeA[5][3], eeB[5][3];
        fk_ee(poseA + (size_t)frame * 144, offA + (size_t)frame * 72, eeA);
        fk_ee(poseB + (size_t)frame * 144, offB + (size_t)frame * 72, eeB);
#pragma unroll
        for (int e = 0; e < 5; ++e) {
#pragma unroll
            for (int a = 0; a < 3; ++a) {
                const float d = eeA[e][a] * s_iSA[a]
                              - eeB[e][a] * s_iSB[a]
                              - s_c[e * 3 + a];
                s = fmaf(d, d, s);
            }
        }
    }

    // deterministic in-block reduction
#pragma unroll
    for (int o = 16; o > 0; o >>= 1)
        s += __shfl_xor_sync(0xFFFFFFFFu, s, o);
    const int wid  = threadIdx.x >> 5;
    const int lane = threadIdx.x & 31;
    if (lane == 0) s_wsum[wid] = s;
    __syncthreads();

    if (threadIdx.x == 0) {
        g_partials[blockIdx.x] = s_wsum[0] + s_wsum[1] + s_wsum[2] + s_wsum[3];
        __threadfence();
        const unsigned int done = atomicAdd(&g_count, 1u);
        s_last = (done == (unsigned int)(nb - 1));
    }
    __syncthreads();

    // Last block to finish reduces all partials in a FIXED order
    // (independent of which block it is) -> deterministic; writes d_out
    // directly so the graph has a single kernel node.
    if (s_last) {
        double ds = 0.0;
        for (int i = threadIdx.x; i < nb; i += 128)
            ds += (double)g_partials[i];
        s_dsum[threadIdx.x] = ds;
        __syncthreads();
#pragma unroll
        for (int k = 64; k > 0; k >>= 1) {
            if (threadIdx.x < k) s_dsum[threadIdx.x] += s_dsum[threadIdx.x + k];
            __syncthreads();
        }
        if (threadIdx.x == 0) {
            out[0] = (float)(s_dsum[0] * (double)inv_count);
            g_count = 0;   // reset for the next graph replay
        }
    }
}

extern "C" void kernel_launch(void* const* d_in, const int* in_sizes, int n_in,
                              void* d_out, int out_size)
{
    const float* poseA = (const float*)d_in[0];
    const float* poseB = (const float*)d_in[1];
    const float* offA  = (const float*)d_in[2];
    const float* offB  = (const float*)d_in[3];
    const float* tA    = (const float*)d_in[4];
    const float* tB    = (const float*)d_in[5];
    float* out = (float*)d_out;

    const int F = in_sizes[0] / (NJ * 6);
    const int threads = 128;
    const int nb = (F + threads - 1) / threads;
    const float inv_count = 1.0f / ((float)F * 15.0f);

    ee_loss_kernel<<<nb, threads>>>(poseA, poseB, offA, offB, tA, tB, out, F, nb, inv_count);
}